// round 2
// baseline (speedup 1.0000x reference)
#include <cuda_runtime.h>
#include <cuda_bf16.h>

// Fixed problem shapes (from reference setup_inputs)
#define B_  4
#define T_  16
#define O_  32
#define H_  181
#define W_  360
#define BT_ (B_ * T_)          // 64 images
#define P_  (BT_ * O_)         // 2048 trajectory points
#define HW_ (H_ * W_)          // 65160 px per image

// exp(-0.5 * d^2 / (sigma^2 + eps))  -> coefficient on d^2
#define GAUSS_C (-0.5f / (2.5f * 2.5f + 1e-8f))
#define EPS_    1e-8f

#define TILE_H  16
#define NTILES  ((H_ + TILE_H - 1) / TILE_H)   // 12

// Scratch (no allocations allowed anywhere)
__device__ float        g_explat[P_ * H_];   // [point][h]
__device__ float        g_explon[P_ * W_];   // [point][w]
__device__ unsigned int g_maxbits[BT_];      // per-image max, float bits (>=0)

// ---------------------------------------------------------------------------
// Kernel A: separable exp tables + zero the per-image max accumulators.
// grid = P_ blocks, 256 threads. Each block owns one (img, o) point.
// ---------------------------------------------------------------------------
__global__ void traj_tables_kernel(const float* __restrict__ traj,
                                   const float* __restrict__ lat,
                                   const float* __restrict__ lon)
{
    const int p = blockIdx.x;                 // 0..P_-1
    const float lat_t = traj[p * 2 + 0];
    const float lon_t = traj[p * 2 + 1];

    if (p < BT_ && threadIdx.x == 0) g_maxbits[p] = 0u;

    for (int i = threadIdx.x; i < H_ + W_; i += blockDim.x) {
        if (i < H_) {
            float d = lat[i] - lat_t;
            g_explat[p * H_ + i] = __expf(GAUSS_C * d * d);
        } else {
            int j = i - H_;
            float d = lon[j] - lon_t;
            g_explon[p * W_ + j] = __expf(GAUSS_C * d * d);
        }
    }
}

// ---------------------------------------------------------------------------
// Kernel B: rank-32 outer-product accumulation per image tile + max reduce.
// grid = (NTILES, BT_), block = 256.
// smem: slon[32][360] (45KB) + slat[32][16] (2KB) + 32-float reduction buf.
// Each thread handles float4 column groups: per o, 1 broadcast LDS (slat)
// + 1 LDS.128 (slon) + 4 FFMA.
// ---------------------------------------------------------------------------
__global__ __launch_bounds__(256)
void traj_accum_kernel(float* __restrict__ out)
{
    __shared__ float slon[O_ * W_];        // 46080 B
    __shared__ float slat[O_ * TILE_H];    //  2048 B
    __shared__ float sred[32];

    const int img  = blockIdx.y;
    const int r0   = blockIdx.x * TILE_H;
    const int tid  = threadIdx.x;

    // Stage lon tables for all 32 points of this image
    {
        const float* src = g_explon + img * (O_ * W_);
        for (int i = tid; i < O_ * W_; i += 256) slon[i] = src[i];
    }
    // Stage lat tables for this row tile
    {
        const float* src = g_explat + img * (O_ * H_);
        for (int i = tid; i < O_ * TILE_H; i += 256) {
            int o = i / TILE_H, r = i % TILE_H;
            int h = r0 + r;
            slat[i] = (h < H_) ? src[o * H_ + h] : 0.0f;
        }
    }
    __syncthreads();

    const int nrows = min(TILE_H, H_ - r0);
    const int nquads = nrows * (W_ / 4);   // W_=360 -> 90 quads/row
    float* outimg = out + img * HW_;

    float lmax = 0.0f;
    for (int idx = tid; idx < nquads; idx += 256) {
        const int r  = idx / (W_ / 4);
        const int cq = idx % (W_ / 4);

        float4 acc = make_float4(0.f, 0.f, 0.f, 0.f);
        #pragma unroll
        for (int o = 0; o < O_; o++) {
            const float  a = slat[o * TILE_H + r];
            const float4 v = *reinterpret_cast<const float4*>(&slon[o * W_ + cq * 4]);
            acc.x = fmaf(a, v.x, acc.x);
            acc.y = fmaf(a, v.y, acc.y);
            acc.z = fmaf(a, v.z, acc.z);
            acc.w = fmaf(a, v.w, acc.w);
        }
        *reinterpret_cast<float4*>(&outimg[(r0 + r) * W_ + cq * 4]) = acc;
        lmax = fmaxf(lmax, fmaxf(fmaxf(acc.x, acc.y), fmaxf(acc.z, acc.w)));
    }

    // Block max reduction
    #pragma unroll
    for (int off = 16; off > 0; off >>= 1)
        lmax = fmaxf(lmax, __shfl_xor_sync(0xFFFFFFFFu, lmax, off));
    if ((tid & 31) == 0) sred[tid >> 5] = lmax;
    __syncthreads();
    if (tid < 32) {
        float v = (tid < (256 / 32)) ? sred[tid] : 0.0f;
        #pragma unroll
        for (int off = 4; off > 0; off >>= 1)
            v = fmaxf(v, __shfl_xor_sync(0xFFFFFFFFu, v, off));
        if (tid == 0)
            atomicMax(reinterpret_cast<int*>(&g_maxbits[img]), __float_as_int(v));
    }
}

// ---------------------------------------------------------------------------
// Kernel C: normalize by per-image max (+eps). float4 grid-stride.
// ---------------------------------------------------------------------------
__global__ __launch_bounds__(256)
void traj_norm_kernel(float* __restrict__ out)
{
    const int n4 = (BT_ * HW_) / 4;        // HW_ divisible by 4
    const int q4 = HW_ / 4;
    for (int i = blockIdx.x * blockDim.x + threadIdx.x; i < n4;
         i += gridDim.x * blockDim.x) {
        const int img = i / q4;
        const float m = __int_as_float((int)g_maxbits[img]);
        const float inv = 1.0f / (m + EPS_);
        float4 v = reinterpret_cast<float4*>(out)[i];
        v.x *= inv; v.y *= inv; v.z *= inv; v.w *= inv;
        reinterpret_cast<float4*>(out)[i] = v;
    }
}

// ---------------------------------------------------------------------------
extern "C" void kernel_launch(void* const* d_in, const int* in_sizes, int n_in,
                              void* d_out, int out_size)
{
    const float* traj = (const float*)d_in[0];  // (4,16,32,2)
    const float* lat  = (const float*)d_in[1];  // (181,)
    const float* lon  = (const float*)d_in[2];  // (360,)
    float* out = (float*)d_out;                 // (64,181,360)

    traj_tables_kernel<<<P_, 256>>>(traj, lat, lon);

    dim3 grid_b(NTILES, BT_);
    traj_accum_kernel<<<grid_b, 256>>>(out);

    const int n4 = (BT_ * HW_) / 4;
    int blocks = (n4 + 255) / 256;
    if (blocks > 4096) blocks = 4096;
    traj_norm_kernel<<<blocks, 256>>>(out);
}

// round 4
// speedup vs baseline: 1.9227x; 1.9227x over previous
#include <cuda_runtime.h>
#include <cuda_bf16.h>

// Fixed problem shapes
#define B_  4
#define T_  16
#define O_  32
#define H_  181
#define W_  360
#define BT_ (B_ * T_)          // 64 images
#define P_  (BT_ * O_)         // 2048 points
#define HW_ (H_ * W_)          // 65160 px

#define GAUSS_C (-0.5f / (2.5f * 2.5f + 1e-8f))
#define EPS_    1e-8f

// Windowed tables: 48 slots, valid window at slots [8..40] (33 grid indices),
// slot s <-> grid index start + s - 8. Slots outside hold 0 (zero padding for
// branchless clamped reads).
#define WSLOT 48

__device__ float        g_latw[P_ * WSLOT];
__device__ float        g_lonw[P_ * WSLOT];
__device__ int          g_latstart[P_];
__device__ int          g_lonstart[P_];
__device__ unsigned int g_maxbits[BT_];

// ---------------------------------------------------------------------------
// Kernel A: windowed exp tables (+ zero per-image max accumulators).
// grid = P_ blocks, 96 threads: t<48 -> lat slot t, t>=48 -> lon slot t-48.
// ---------------------------------------------------------------------------
__global__ void traj_tables_kernel(const float* __restrict__ traj,
                                   const float* __restrict__ lat,
                                   const float* __restrict__ lon)
{
    const int p = blockIdx.x;
    const float lat_t = traj[p * 2 + 0];
    const float lon_t = traj[p * 2 + 1];

    // lat grid: -90 + i (step 1.0); lon grid: -180 + i*(360/359)
    const int lat_start = (int)floorf(lat_t + 90.0f) - 16;
    const int lon_start = (int)floorf((lon_t + 180.0f) * (359.0f / 360.0f)) - 16;

    if (threadIdx.x == 0) {
        g_latstart[p] = lat_start;
        g_lonstart[p] = lon_start;
        if (p < BT_) g_maxbits[p] = 0u;
    }

    const int t = threadIdx.x;
    if (t < WSLOT) {
        int gi = lat_start + t - 8;
        float v = 0.0f;
        if (t >= 8 && t <= 40 && gi >= 0 && gi < H_) {
            float d = lat[gi] - lat_t;
            v = __expf(GAUSS_C * d * d);
        }
        g_latw[p * WSLOT + t] = v;
    } else if (t < 2 * WSLOT) {
        int s = t - WSLOT;
        int gi = lon_start + s - 8;
        float v = 0.0f;
        if (s >= 8 && s <= 40 && gi >= 0 && gi < W_) {
            float d = lon[gi] - lon_t;
            v = __expf(GAUSS_C * d * d);
        }
        g_lonw[p * WSLOT + s] = v;
    }
}

// ---------------------------------------------------------------------------
// Kernel B: windowed gather, register tile 4 rows x 8 cols per thread.
// Block = 128 threads (4 warps), block patch = 32 rows x 128 cols.
// Warp patch = 16 rows x 64 cols (compact -> small per-warp active-o union).
// grid = (3 col-patches, 6 row-patches, 64 images).
// ---------------------------------------------------------------------------
__global__ __launch_bounds__(128)
void traj_accum_kernel(float* __restrict__ out)
{
    __shared__ float slatw[O_ * WSLOT];   // 6 KB
    __shared__ float slonw[O_ * WSLOT];   // 6 KB
    __shared__ int   slats[O_];
    __shared__ int   slons[O_];
    __shared__ float sred[4];

    const int img = blockIdx.z;
    const int tid = threadIdx.x;

    // Stage this image's windowed tables
    {
        const float* glat = g_latw + img * (O_ * WSLOT);
        const float* glon = g_lonw + img * (O_ * WSLOT);
        for (int i = tid; i < O_ * WSLOT; i += 128) {
            slatw[i] = glat[i];
            slonw[i] = glon[i];
        }
        if (tid < O_) {
            slats[tid] = g_latstart[img * O_ + tid];
            slons[tid] = g_lonstart[img * O_ + tid];
        }
    }
    __syncthreads();

    const int w  = tid >> 5, l = tid & 31;
    const int wr = w >> 1, wc = w & 1;
    const int rg = l >> 3, cg = l & 7;
    const int R0 = blockIdx.y * 32 + wr * 16 + rg * 4;
    const int C0 = blockIdx.x * 128 + wc * 64 + cg * 8;

    float acc[4][8];
    #pragma unroll
    for (int j = 0; j < 4; j++)
        #pragma unroll
        for (int k = 0; k < 8; k++) acc[j][k] = 0.0f;

    for (int o = 0; o < O_; o++) {
        const int ls = slats[o], cs = slons[o];
        // window covers grid indices [start, start+32]
        if (R0 + 3 < ls || R0 > ls + 32 || C0 + 7 < cs || C0 > cs + 32) continue;

        float a[4], v[8];
        #pragma unroll
        for (int j = 0; j < 4; j++) {
            int idx = min(max(R0 + j - ls + 8, 0), WSLOT - 1);
            a[j] = slatw[o * WSLOT + idx];
        }
        #pragma unroll
        for (int k = 0; k < 8; k++) {
            int idx = min(max(C0 + k - cs + 8, 0), WSLOT - 1);
            v[k] = slonw[o * WSLOT + idx];
        }
        #pragma unroll
        for (int j = 0; j < 4; j++)
            #pragma unroll
            for (int k = 0; k < 8; k++)
                acc[j][k] = fmaf(a[j], v[k], acc[j][k]);
    }

    // Write (coalesced float4 pairs) + local max
    float lmax = 0.0f;
    float* oimg = out + img * HW_;
    const bool colok = (C0 < W_);   // C0 multiple of 8; 8-col group all-in or all-out
    #pragma unroll
    for (int j = 0; j < 4; j++) {
        const int r = R0 + j;
        if (colok && r < H_) {
            float4 v0 = make_float4(acc[j][0], acc[j][1], acc[j][2], acc[j][3]);
            float4 v1 = make_float4(acc[j][4], acc[j][5], acc[j][6], acc[j][7]);
            *reinterpret_cast<float4*>(&oimg[r * W_ + C0])     = v0;
            *reinterpret_cast<float4*>(&oimg[r * W_ + C0 + 4]) = v1;
            float m0 = fmaxf(fmaxf(v0.x, v0.y), fmaxf(v0.z, v0.w));
            float m1 = fmaxf(fmaxf(v1.x, v1.y), fmaxf(v1.z, v1.w));
            lmax = fmaxf(lmax, fmaxf(m0, m1));
        }
    }

    #pragma unroll
    for (int off = 16; off > 0; off >>= 1)
        lmax = fmaxf(lmax, __shfl_xor_sync(0xFFFFFFFFu, lmax, off));
    if (l == 0) sred[w] = lmax;
    __syncthreads();
    if (tid == 0) {
        float m = fmaxf(fmaxf(sred[0], sred[1]), fmaxf(sred[2], sred[3]));
        atomicMax(reinterpret_cast<int*>(&g_maxbits[img]), __float_as_int(m));
    }
}

// ---------------------------------------------------------------------------
// Kernel C: normalize by per-image max (+eps). float4 grid-stride, L2-resident.
// ---------------------------------------------------------------------------
__global__ __launch_bounds__(256)
void traj_norm_kernel(float* __restrict__ out)
{
    const int n4 = (BT_ * HW_) / 4;
    const int q4 = HW_ / 4;
    for (int i = blockIdx.x * blockDim.x + threadIdx.x; i < n4;
         i += gridDim.x * blockDim.x) {
        const int img = i / q4;
        const float m = __int_as_float((int)g_maxbits[img]);
        const float inv = 1.0f / (m + EPS_);
        float4 v = reinterpret_cast<float4*>(out)[i];
        v.x *= inv; v.y *= inv; v.z *= inv; v.w *= inv;
        reinterpret_cast<float4*>(out)[i] = v;
    }
}

// ---------------------------------------------------------------------------
extern "C" void kernel_launch(void* const* d_in, const int* in_sizes, int n_in,
                              void* d_out, int out_size)
{
    const float* traj = (const float*)d_in[0];  // (4,16,32,2)
    const float* lat  = (const float*)d_in[1];  // (181,)
    const float* lon  = (const float*)d_in[2];  // (360,)
    float* out = (float*)d_out;                 // (64,181,360) f32

    traj_tables_kernel<<<P_, 96>>>(traj, lat, lon);

    dim3 grid_b(3, 6, BT_);   // 3 col-patches x 6 row-patches x 64 images
    traj_accum_kernel<<<grid_b, 128>>>(out);

    const int n4 = (BT_ * HW_) / 4;
    int blocks = (n4 + 255) / 256;
    if (blocks > 2048) blocks = 2048;
    traj_norm_kernel<<<blocks, 256>>>(out);
}